// round 6
// baseline (speedup 1.0000x reference)
#include <cuda_runtime.h>
#include <cuda_fp16.h>

#define NN    100000
#define NE    3200000
#define ETOT  (NE + NN)
#define SCAN_B 512
#define NBLK   ((NN + SCAN_B - 1) / SCAN_B)   // 196

// ---------------- scratch (device globals; allocation-free) ----------------
__device__ __align__(16) __half g_hh[NN * 32];    // per-node features, fp16 (edge-pass gather)
__device__ __align__(16) float g_agg[NN * 32];    // aggregated output, layers 1-2 (fp32)
__device__ __align__(16) float g_agg2[NN * 16];   // aggregated output, layer 3 (fp32)
__device__ __align__(8)  float g_asrc[NN * 2];    // alpha_src per node per head (fp32)
__device__ __align__(8)  float g_adst[NN * 2];    // alpha_dst per node per head (fp32)
__device__ __align__(8)  float g_sum[NN * 2];     // softmax denominator per dst per head
__device__ int g_csr_src[ETOT];                   // src ids grouped by dst
__device__ int g_cnt[NN];
__device__ int g_off[NN + 1];
__device__ int g_cur[NN];
__device__ int g_bsum[NBLK];
__device__ int g_boff[NBLK];
__device__ int g_is64;

// ---------------- dtype probe: int64 arrays have zero odd 32-bit words ------
__global__ void probe_dtype(const int* __restrict__ ei32) {
    __shared__ int nz;
    if (threadIdx.x == 0) nz = 0;
    __syncthreads();
    int v = ei32[2 * threadIdx.x + 1];
    if (v != 0) atomicOr(&nz, 1);
    __syncthreads();
    if (threadIdx.x == 0) g_is64 = (nz == 0) ? 1 : 0;
}

__global__ __launch_bounds__(256) void zero_cnt(int n) {
    int i = blockIdx.x * 256 + threadIdx.x;
    if (i < n) g_cnt[i] = 0;
}

// ---------------- dst histogram straight from edge_index --------------------
__global__ __launch_bounds__(256) void hist(const void* __restrict__ ei, int E, int n) {
    int i = blockIdx.x * 256 + threadIdx.x;
    int d;
    if (i < E) {
        d = g_is64 ? (int)((const long long*)ei)[E + i] : ((const int*)ei)[E + i];
    } else if (i < E + n) {
        d = i - E;
    } else return;
    atomicAdd(&g_cnt[d], 1);
}

// ---------------- 3-kernel exclusive scan of g_cnt -> g_off -----------------
__global__ __launch_bounds__(SCAN_B) void scan1(int n) {
    __shared__ int sm[SCAN_B];
    int t = threadIdx.x, i = blockIdx.x * SCAN_B + t;
    int v = (i < n) ? g_cnt[i] : 0;
    sm[t] = v; __syncthreads();
#pragma unroll
    for (int o = 1; o < SCAN_B; o <<= 1) {
        int x = (t >= o) ? sm[t - o] : 0;
        __syncthreads();
        sm[t] += x;
        __syncthreads();
    }
    if (i < n) g_off[i] = sm[t] - v;
    if (t == SCAN_B - 1) g_bsum[blockIdx.x] = sm[t];
}

__global__ void scan2(int nb) {
    __shared__ int sm[256];
    int t = threadIdx.x;
    int v = (t < nb) ? g_bsum[t] : 0;
    sm[t] = v; __syncthreads();
#pragma unroll
    for (int o = 1; o < 256; o <<= 1) {
        int x = (t >= o) ? sm[t - o] : 0;
        __syncthreads();
        sm[t] += x;
        __syncthreads();
    }
    if (t < nb) g_boff[t] = sm[t] - v;
}

__global__ __launch_bounds__(256) void scan3(int n, int etot) {
    int i = blockIdx.x * 256 + threadIdx.x;
    if (i < n) {
        int v = g_off[i] + g_boff[i / SCAN_B];
        g_off[i] = v;
        g_cur[i] = v;
    }
    if (i == 0) g_off[n] = etot;
}

// ---------------- scatter straight from edge_index --------------------------
__global__ __launch_bounds__(256) void scatter(const void* __restrict__ ei, int E, int n) {
    int i = blockIdx.x * 256 + threadIdx.x;
    int s, d;
    if (i < E) {
        if (g_is64) {
            const long long* p = (const long long*)ei;
            s = (int)p[i]; d = (int)p[E + i];
        } else {
            const int* p = (const int*)ei;
            s = p[i]; d = p[E + i];
        }
    } else if (i < E + n) {
        s = d = i - E;
    } else return;
    int p = atomicAdd(&g_cur[d], 1);
    g_csr_src[p] = s;
}

// ---------------- fp16 row store helper -------------------------------------
template <int OUT>
__device__ __forceinline__ void store_h_fp16(__half* dst, const float* h) {
#pragma unroll
    for (int k = 0; k < OUT / 8; k++) {
        __half2 p0 = __floats2half2_rn(h[8 * k + 0], h[8 * k + 1]);
        __half2 p1 = __floats2half2_rn(h[8 * k + 2], h[8 * k + 3]);
        __half2 p2 = __floats2half2_rn(h[8 * k + 4], h[8 * k + 5]);
        __half2 p3 = __floats2half2_rn(h[8 * k + 6], h[8 * k + 7]);
        uint4 u;
        u.x = *(unsigned*)&p0; u.y = *(unsigned*)&p1;
        u.z = *(unsigned*)&p2; u.w = *(unsigned*)&p3;
        ((uint4*)dst)[k] = u;
    }
}

// ---------------- layer-1 node pass (IN=3, OUT=32, H=2, C=16) ---------------
__global__ __launch_bounds__(256) void node_pass1(const float* __restrict__ x,
                                                  const float* __restrict__ W,
                                                  const float* __restrict__ aw,
                                                  const float* __restrict__ dw,
                                                  int n) {
    __shared__ float sW[3 * 32];
    __shared__ float sA[32], sB[32];
    int t = threadIdx.x;
    if (t < 96) sW[t] = W[t];
    if (t < 32) { sA[t] = aw[t]; sB[t] = dw[t]; }
    __syncthreads();
    int i = blockIdx.x * 256 + t;
    if (i >= n) return;

    float x0 = x[3 * i], x1 = x[3 * i + 1], x2 = x[3 * i + 2];
    float h[32];
#pragma unroll
    for (int o = 0; o < 32; o++)
        h[o] = x0 * sW[o] + x1 * sW[32 + o] + x2 * sW[64 + o];

    store_h_fp16<32>(g_hh + (size_t)i * 32, h);

    float a0 = 0.f, a1 = 0.f, d0 = 0.f, d1 = 0.f;
#pragma unroll
    for (int c = 0; c < 16; c++) {
        a0 += h[c] * sA[c];           d0 += h[c] * sB[c];
        a1 += h[16 + c] * sA[16 + c]; d1 += h[16 + c] * sB[16 + c];
    }
    g_asrc[2 * i] = a0; g_asrc[2 * i + 1] = a1;
    g_adst[2 * i] = d0; g_adst[2 * i + 1] = d1;
}

// ---------------- node pass layers 2/3: divide + bias + elu + GEMM ----------
template <int IN, int OUT, int H>
__global__ __launch_bounds__(256) void node_passN(const float* __restrict__ W,
                                                  const float* __restrict__ aw,
                                                  const float* __restrict__ dw,
                                                  const float* __restrict__ bias_prev,
                                                  int n) {
    __shared__ float sW[IN * OUT];
    __shared__ float sA[OUT], sB[OUT], sBias[IN];
    for (int j = threadIdx.x; j < IN * OUT; j += 256) sW[j] = W[j];
    if (threadIdx.x < OUT) { sA[threadIdx.x] = aw[threadIdx.x]; sB[threadIdx.x] = dw[threadIdx.x]; }
    if (threadIdx.x < IN)  sBias[threadIdx.x] = bias_prev[threadIdx.x];
    __syncthreads();
    int i = blockIdx.x * 256 + threadIdx.x;
    if (i >= n) return;

    float inv0 = 1.f / (g_sum[2 * i] + 1e-16f);
    float inv1 = 1.f / (g_sum[2 * i + 1] + 1e-16f);

    float feat[IN];
#pragma unroll
    for (int c = 0; c < IN; c++) {
        float v = g_agg[(size_t)i * IN + c] * ((c < IN / 2) ? inv0 : inv1) + sBias[c];
        feat[c] = (v > 0.f) ? v : expm1f(v);   // elu
    }

    float h[OUT];
#pragma unroll
    for (int o = 0; o < OUT; o++) h[o] = 0.f;
#pragma unroll
    for (int c = 0; c < IN; c++) {
        float f = feat[c];
#pragma unroll
        for (int o = 0; o < OUT; o++) h[o] += f * sW[c * OUT + o];
    }

    store_h_fp16<OUT>(g_hh + (size_t)i * OUT, h);

    if (H == 2) {
        float a0 = 0.f, a1 = 0.f, d0 = 0.f, d1 = 0.f;
#pragma unroll
        for (int c = 0; c < 16; c++) {
            a0 += h[c] * sA[c];            d0 += h[c] * sB[c];
            a1 += h[16 + c] * sA[16 + c];  d1 += h[16 + c] * sB[16 + c];
        }
        g_asrc[2 * i] = a0; g_asrc[2 * i + 1] = a1;
        g_adst[2 * i] = d0; g_adst[2 * i + 1] = d1;
    } else {
        float a0 = 0.f, d0 = 0.f;
#pragma unroll
        for (int c = 0; c < 16; c++) { a0 += h[c] * sA[c]; d0 += h[c] * sB[c]; }
        g_asrc[2 * i] = a0; g_asrc[2 * i + 1] = 0.f;
        g_adst[2 * i] = d0; g_adst[2 * i + 1] = 0.f;
    }
}

// ---------------- CSR edge pass: warp per dst, fp16 gather ------------------
// OUT/8 lanes per edge; each lane holds 8 fp32 accumulators. No atomics.
template <int OUT, int H, bool TO2>
__global__ __launch_bounds__(256) void edge_csr(int n) {
    constexpr int LPE = OUT / 8;   // lanes per edge (4 or 2)
    constexpr int EPW = 32 / LPE;  // edges in flight per warp (8 or 16)
    int warp = (blockIdx.x * 256 + threadIdx.x) >> 5;
    if (warp >= n) return;
    int d = warp;
    int lane = threadIdx.x & 31;
    int grp = lane / LPE;
    int l = lane % LPE;

    int start = g_off[d];
    int end   = g_off[d + 1];
    float2 ad = *(const float2*)(g_adst + 2 * d);

    float acc[8];
#pragma unroll
    for (int k = 0; k < 8; k++) acc[k] = 0.f;
    float ws0 = 0.f, ws1 = 0.f;

    for (int e = start + grp; e < end; e += EPW) {
        int s = g_csr_src[e];
        float2 as = *(const float2*)(g_asrc + 2 * s);

        float e0 = as.x + ad.x;
        e0 = fmaxf(e0, 0.2f * e0);             // leaky_relu(·, 0.2)
        float w0 = __expf(e0);
        float w1 = 0.f;
        if (H == 2) {
            float e1 = as.y + ad.y;
            e1 = fmaxf(e1, 0.2f * e1);
            w1 = __expf(e1);
        }
        if (l == 0) { ws0 += w0; ws1 += w1; }

        float w = (H == 2 && l >= LPE / 2) ? w1 : w0;
        uint4 u = ((const uint4*)(g_hh + (size_t)s * OUT))[l];
        float2 f0 = __half22float2(*(__half2*)&u.x);
        float2 f1 = __half22float2(*(__half2*)&u.y);
        float2 f2 = __half22float2(*(__half2*)&u.z);
        float2 f3 = __half22float2(*(__half2*)&u.w);
        acc[0] += f0.x * w; acc[1] += f0.y * w;
        acc[2] += f1.x * w; acc[3] += f1.y * w;
        acc[4] += f2.x * w; acc[5] += f2.y * w;
        acc[6] += f3.x * w; acc[7] += f3.y * w;
    }

    // reduce across edge groups (lanes with equal l)
#pragma unroll
    for (int off = LPE; off < 32; off <<= 1) {
#pragma unroll
        for (int k = 0; k < 8; k++)
            acc[k] += __shfl_xor_sync(0xffffffffu, acc[k], off);
        ws0 += __shfl_xor_sync(0xffffffffu, ws0, off);
        if (H == 2) ws1 += __shfl_xor_sync(0xffffffffu, ws1, off);
    }

    if (lane < LPE) {
        float* op = (TO2 ? g_agg2 : g_agg) + (size_t)d * OUT + l * 8;
        ((float4*)op)[0] = make_float4(acc[0], acc[1], acc[2], acc[3]);
        ((float4*)op)[1] = make_float4(acc[4], acc[5], acc[6], acc[7]);
    }
    if (lane == 0) {
        g_sum[2 * d]     = ws0;
        g_sum[2 * d + 1] = (H == 2) ? ws1 : 0.f;
    }
}

// ---------------- finalize: divide + bias + elu -> embeddings; sigmoid head -
__global__ __launch_bounds__(256) void finalize(const float* __restrict__ b3,
                                                const float* __restrict__ Wout,
                                                const float* __restrict__ bout,
                                                float* __restrict__ out, int n) {
    __shared__ float sb[16], sw[16];
    if (threadIdx.x < 16) { sb[threadIdx.x] = b3[threadIdx.x]; sw[threadIdx.x] = Wout[threadIdx.x]; }
    __syncthreads();
    int i = blockIdx.x * 256 + threadIdx.x;
    if (i >= n) return;

    float inv = 1.f / (g_sum[2 * i] + 1e-16f);
    float acc = 0.f;
    float* eo = out + n + (size_t)i * 16;
#pragma unroll
    for (int c = 0; c < 16; c++) {
        float v = g_agg2[(size_t)i * 16 + c] * inv + sb[c];
        v = (v > 0.f) ? v : expm1f(v);         // elu -> embedding
        eo[c] = v;
        acc += v * sw[c];
    }
    out[i] = 1.f / (1.f + __expf(-(acc + bout[0])));
}

// ---------------- launch -----------------------------------------------------
extern "C" void kernel_launch(void* const* d_in, const int* in_sizes, int n_in,
                              void* d_out, int out_size) {
    const float* x  = (const float*)d_in[0];
    const void*  ei = d_in[1];
    const float *W1 = (const float*)d_in[2],  *as1 = (const float*)d_in[3],
                *ad1 = (const float*)d_in[4], *b1  = (const float*)d_in[5];
    const float *W2 = (const float*)d_in[6],  *as2 = (const float*)d_in[7],
                *ad2 = (const float*)d_in[8], *b2  = (const float*)d_in[9];
    const float *W3 = (const float*)d_in[10], *as3 = (const float*)d_in[11],
                *ad3 = (const float*)d_in[12], *b3 = (const float*)d_in[13];
    const float *Wout = (const float*)d_in[14], *bout = (const float*)d_in[15];

    int n    = in_sizes[0] / 3;
    int E    = in_sizes[1] / 2;
    int etot = E + n;
    int nb = (n + 255) / 256;
    int eb = (etot + 255) / 256;
    int wb = (n * 32 + 255) / 256;          // warp-per-node grids
    int sb = (n + SCAN_B - 1) / SCAN_B;

    // ---- CSR build (graph is layer-invariant; built once per launch) ----
    probe_dtype<<<1, 256>>>((const int*)ei);
    zero_cnt<<<nb, 256>>>(n);
    hist<<<eb, 256>>>(ei, E, n);
    scan1<<<sb, SCAN_B>>>(n);
    scan2<<<1, 256>>>(sb);
    scan3<<<nb, 256>>>(n, etot);
    scatter<<<eb, 256>>>(ei, E, n);

    // ---- layer 1 ----
    node_pass1<<<nb, 256>>>(x, W1, as1, ad1, n);
    edge_csr<32, 2, false><<<wb, 256>>>(n);

    // ---- layer 2 ----
    node_passN<32, 32, 2><<<nb, 256>>>(W2, as2, ad2, b1, n);
    edge_csr<32, 2, false><<<wb, 256>>>(n);

    // ---- layer 3 ----
    node_passN<32, 16, 1><<<nb, 256>>>(W3, as3, ad3, b2, n);
    edge_csr<16, 1, true><<<wb, 256>>>(n);

    // ---- output head ----
    finalize<<<nb, 256>>>(b3, Wout, bout, (float*)d_out, n);
}